// round 9
// baseline (speedup 1.0000x reference)
#include <cuda_runtime.h>

// ---------------- problem constants ----------------
#define M0 76800
#define M1 19200
#define M2 4800
#define NANCH (M0 + M1 + M2)
#define K_LEV 1000
#define K_TOT 3000
#define HB 8192               // histogram bins (approx squared-score space)
#define NREP 8                // histogram replicas (anti-contention)
#define CAP 16384             // final candidate buffer per level
#define CAPB 2000000          // survivor buffer per level
#define BIN_BASE2 0x3ED851ECu // bits of 0.4225f (= 0.65^2)
#define BIN_SH2 11
#define NCLS 80
#define FILT_GRID 1184
#define FILT_BLK 256
#define FILT_STRIDE (FILT_GRID * FILT_BLK)
#define ACC_CAP 96

// ---------------- device scratch (static — no allocations) ----------------
__device__ unsigned int        d_hist[3][NREP][HB];
__device__ int                 d_T[3];
__device__ int                 d_cnt[3];     // final per-level candidate counts
__device__ int                 d_cnt2[3];    // survivor buffer counts
__device__ __align__(16) unsigned long long d_bufA[3][CAPB]; // (p_bits<<32)|idx
__device__ unsigned long long  d_buf[3][CAP];   // exact: (s_bits<<32)|~idx
__device__ unsigned long long  d_top[3][K_LEV];
__device__ float               d_sobj[NANCH];
__device__ float               d_cmin[NANCH];

__constant__ float c_anch[3][3][2] = {
    {{10.f,13.f},{16.f,30.f},{33.f,23.f}},
    {{30.f,61.f},{62.f,45.f},{59.f,119.f}},
    {{116.f,90.f},{156.f,198.f},{373.f,326.f}}};

// --------- XLA:CPU vectorized exp (Eigen/Cephes) — EXACT path ---------
__device__ __forceinline__ float xla_expf(float x) {
    float in = x;
    x = fminf(x, 88.3762626647950f);
    x = fmaxf(x, -88.3762626647949f);
    float fx = floorf(__fadd_rn(__fmul_rn(x, 1.44269504088896341f), 0.5f));
    float tmp = __fmul_rn(fx, 0.693359375f);
    float z   = __fmul_rn(fx, -2.12194440e-4f);
    float r   = __fsub_rn(__fsub_rn(x, tmp), z);
    float r2  = __fmul_rn(r, r);
    float y = 1.9875691500E-4f;
    y = __fadd_rn(__fmul_rn(y, r), 1.3981999507E-3f);
    y = __fadd_rn(__fmul_rn(y, r), 8.3334519073E-3f);
    y = __fadd_rn(__fmul_rn(y, r), 4.1665795894E-2f);
    y = __fadd_rn(__fmul_rn(y, r), 1.6666665459E-1f);
    y = __fadd_rn(__fmul_rn(y, r), 5.0000001201E-1f);
    y = __fadd_rn(__fmul_rn(y, r2), r);
    y = __fadd_rn(y, 1.0f);
    int m = (int)fx;
    float p2m = __int_as_float((m + 127) << 23);
    return fmaxf(__fmul_rn(y, p2m), in);
}

__device__ __forceinline__ float sigm(float x) {           // exact (Cephes)
    return __fdiv_rn(1.0f, __fadd_rn(1.0f, xla_expf(-x)));
}

__device__ __forceinline__ float sigm_a(float x) {         // fast approx ~1e-6 rel
    return __fdividef(1.0f, 1.0f + __expf(-x));
}

__device__ __forceinline__ int sq_bin(unsigned pbits) {
    return ((int)(pbits - BIN_BASE2)) >> BIN_SH2;
}

// ---------------- no-op (launch-index alignment for ncu) ----------------
__global__ void k_nop() {}

// -------- prep: zero hists/counters + sigmoid(obj) + prefilter bound --------
__global__ void k_prep(const float* __restrict__ o0, const float* __restrict__ o1,
                       const float* __restrict__ o2) {
    int t = blockIdx.x * blockDim.x + threadIdx.x;
    if (t < 3 * NREP * HB / 2) ((unsigned long long*)d_hist)[t] = 0ULL;
    if (t < 3) { d_cnt[t] = 0; d_cnt2[t] = 0; }
    if (t < NANCH) {
        float x;
        if (t < M0)            x = o0[t];
        else if (t < M0 + M1)  x = o1[t - M0];
        else                   x = o2[t - M0 - M1];
        float so = sigm(x);
        d_sobj[t] = so;
        float r = 0.41f / so;
        d_cmin[t] = (r >= 0.999f) ? 3.0e38f : (logf(r / (1.0f - r)) - 1e-2f);
    }
}

// ------ single bulk pass: prefilter, approx product, hist + survivor buffer ------
__global__ void k_filter(const float* __restrict__ c0, const float* __restrict__ c1,
                         const float* __restrict__ c2) {
    const int N4 = (M0 + M1 + M2) * 20;   // 2,016,000 float4 groups
    const int ITERS = (N4 + FILT_STRIDE - 1) / FILT_STRIDE;
    int tid0 = blockIdx.x * blockDim.x + threadIdx.x;
    int lane = threadIdx.x & 31;
    int rep = blockIdx.x & (NREP - 1);
    for (int it = 0; it < ITERS; it++) {
        int idx4 = tid0 + it * FILT_STRIDE;
        bool active = idx4 < N4;
        int lvl = 0, base4 = 0, abase = 0;
        const float* cp = c0;
        if (active) {
            if (idx4 < M0 * 20)             { }
            else if (idx4 < (M0 + M1) * 20) { lvl = 1; base4 = M0 * 20;        abase = M0;      cp = c1; }
            else                            { lvl = 2; base4 = (M0 + M1) * 20; abase = M0 + M1; cp = c2; }
        } else lvl = -1;
        unsigned pb[4]; unsigned pi[4]; int c = 0;
        if (active) {
            int l4 = idx4 - base4;
            int aG = abase + l4 / 20;
            float cmin = __ldg(&d_cmin[aG]);
            float4 cv = __ldg((const float4*)cp + l4);
            float mx = fmaxf(fmaxf(cv.x, cv.y), fmaxf(cv.z, cv.w));
            if (mx >= cmin) {
                float so = __ldg(&d_sobj[aG]);
                float ce[4] = {cv.x, cv.y, cv.z, cv.w};
#pragma unroll
                for (int e = 0; e < 4; e++) {
                    if (ce[e] >= cmin) {
                        float p = so * sigm_a(ce[e]);
                        unsigned pbits = __float_as_uint(p);
                        int b = sq_bin(pbits);
                        if (b >= 0) {
                            if (b > HB - 1) b = HB - 1;
                            atomicAdd(&d_hist[lvl][rep][b], 1u);
                            pb[c] = pbits; pi[c] = (unsigned)(l4 * 4 + e); c++;
                        }
                    }
                }
            }
        }
        // warp-aggregated buffer append (fallback if warp straddles levels)
        unsigned fullm = 0xFFFFFFFFu;
        int l0 = __shfl_sync(fullm, lvl, 0);
        bool uniform = __all_sync(fullm, lvl == l0);
        if (uniform && l0 >= 0) {
            int offs = c;
#pragma unroll
            for (int d = 1; d < 32; d <<= 1) {
                int v = __shfl_up_sync(fullm, offs, d);
                if (lane >= d) offs += v;
            }
            int total = __shfl_sync(fullm, offs, 31);
            int base = 0;
            if (total > 0) {
                if (lane == 31) base = atomicAdd(&d_cnt2[l0], total);
                base = __shfl_sync(fullm, base, 31);
                int excl = offs - c;
                for (int j = 0; j < c; j++) {
                    int p = base + excl + j;
                    if (p < CAPB)
                        d_bufA[l0][p] = ((unsigned long long)pb[j] << 32) | pi[j];
                }
            }
        } else {
            for (int j = 0; j < c; j++) {
                int p = atomicAdd(&d_cnt2[lvl], 1);
                if (p < CAPB)
                    d_bufA[lvl][p] = ((unsigned long long)pb[j] << 32) | pi[j];
            }
        }
    }
}

// ------- threshold bin per level (sum replicas; 2-bin conservative slack) -------
__global__ void k_thresh() {
    int l = blockIdx.x, tid = threadIdx.x;
    __shared__ unsigned int ss[1024];
    __shared__ int smax;
    unsigned c = 0;
#pragma unroll
    for (int b = 0; b < HB / 1024; b++) {
        int bin = tid * (HB / 1024) + b;
        unsigned s = 0;
#pragma unroll
        for (int rp = 0; rp < NREP; rp++) s += d_hist[l][rp][bin];
        c += s;
    }
    ss[tid] = c;
    if (tid == 0) smax = -1;
    __syncthreads();
    for (int offp = 1; offp < 1024; offp <<= 1) {
        unsigned v = ss[tid];
        unsigned a = (tid + offp < 1024) ? ss[tid + offp] : 0u;
        __syncthreads();
        ss[tid] = v + a;
        __syncthreads();
    }
    if (ss[tid] >= (unsigned)K_LEV) atomicMax(&smax, tid);
    __syncthreads();
    if (tid == 0) {
        int cs = (smax < 0) ? 0 : smax;
        const int CH = HB / 1024;
        unsigned acc = (cs < 1023) ? ss[cs + 1] : 0u;
        int T = 0;
        for (int b = cs * CH + CH - 1; b >= cs * CH; b--) {
            unsigned s = 0;
            for (int rp = 0; rp < NREP; rp++) s += d_hist[l][rp][b];
            acc += s;
            if (acc >= (unsigned)K_LEV) { T = b; break; }
        }
        d_T[l] = T - 2;   // slack: approx err (~1e-6 rel) << bin width (2.4e-4 rel)
    }
}

// ------- selection: scan survivor buffer, exact score for bin >= T -------
__device__ __forceinline__ void sel_one(unsigned long long v, int T, int abase,
                                        const float* __restrict__ cp, int lvl) {
    unsigned pbits = (unsigned)(v >> 32);
    if (sq_bin(pbits) >= T) {
        unsigned idx = (unsigned)v;
        float so = __ldg(&d_sobj[abase + idx / 80u]);
        float cl = __ldg(&cp[idx]);
        float s = __fsqrt_rn(__fmul_rn(so, sigm(cl)));
        unsigned bits = __float_as_uint(s);
        int p = atomicAdd(&d_cnt[lvl], 1);
        if (p < CAP)
            d_buf[lvl][p] = ((unsigned long long)bits << 32) |
                            (unsigned long long)(0xFFFFFFFFu - idx);
    }
}

__global__ void k_sel(const float* __restrict__ c0, const float* __restrict__ c1,
                      const float* __restrict__ c2) {
    int gid = blockIdx.x * blockDim.x + threadIdx.x;
    int stride = gridDim.x * blockDim.x;
    for (int lvl = 0; lvl < 3; lvl++) {
        int n = d_cnt2[lvl];
        if (n > CAPB) n = CAPB;
        int T = d_T[lvl];
        const float* cp = (lvl == 0) ? c0 : (lvl == 1 ? c1 : c2);
        int abase = (lvl == 0) ? 0 : (lvl == 1 ? M0 : M0 + M1);
        int half = n >> 1;
        for (int i = gid; i < half; i += stride) {
            ulonglong2 v = *((const ulonglong2*)&d_bufA[lvl][2 * i]);
            sel_one(v.x, T, abase, cp, lvl);
            sel_one(v.y, T, abase, cp, lvl);
        }
        if (gid == 0 && (n & 1)) sel_one(d_bufA[lvl][n - 1], T, abase, cp, lvl);
    }
}

// ---------------- shared-mem bitonic (descending) ----------------
__device__ __forceinline__ void bitonic_desc(unsigned long long* s, int n) {
    for (int k = 2; k <= n; k <<= 1) {
        for (int j = k >> 1; j > 0; j >>= 1) {
            for (int i = threadIdx.x; i < n; i += blockDim.x) {
                int l = i ^ j;
                if (l > i) {
                    unsigned long long a = s[i], b = s[l];
                    bool up = ((i & k) == 0);
                    if (up ? (a < b) : (a > b)) { s[i] = b; s[l] = a; }
                }
            }
            __syncthreads();
        }
    }
}

// ---------------- per-level sort of candidates ----------------
extern __shared__ unsigned long long ssort[];
__global__ void k_sortlvl() {
    int l = blockIdx.x;
    int cnt = d_cnt[l];
    if (cnt > CAP) cnt = CAP;
    int n = 1024;
    while (n < cnt) n <<= 1;
    for (int i = threadIdx.x; i < n; i += blockDim.x)
        ssort[i] = (i < cnt) ? d_buf[l][i] : 0ULL;
    __syncthreads();
    bitonic_desc(ssort, n);
    for (int i = threadIdx.x; i < K_LEV; i += blockDim.x) d_top[l][i] = ssort[i];
}

// --- final: merge (binary search) + decode + per-class NMS + all outputs ---
__global__ void k_final(const float* __restrict__ r0, const float* __restrict__ r1,
                        const float* __restrict__ r2, float* __restrict__ out) {
    extern __shared__ char sfin[];
    unsigned long long* K = (unsigned long long*)sfin;      // [3008]
    float4* s_nbox = (float4*)(K + 3008);                   // [3000]
    float*  s_ar   = (float*)(s_nbox + K_TOT);              // [3000]
    float*  s_sc   = s_ar + K_TOT;                          // [3000]
    int*    s_lb   = (int*)(s_sc + K_TOT);                  // [3000]
    int*    s_acc  = s_lb + K_TOT;                          // [32][ACC_CAP]
    int tid = threadIdx.x;

    for (int i = tid; i < K_TOT; i += blockDim.x) {
        unsigned bits = (unsigned)(d_top[i / 1000][i % 1000] >> 32);
        K[i] = ((unsigned long long)bits << 32) |
               (unsigned long long)(0xFFFFFFFFu - (unsigned)i);
    }
    __syncthreads();
    for (int p = tid; p < K_TOT; p += blockDim.x) {
        unsigned long long kk = K[p];
        int lvl = p / 1000, rk = p % 1000;
        int g = rk;
#pragma unroll
        for (int m = 0; m < 3; m++) {
            if (m == lvl) continue;
            const unsigned long long* L = K + m * 1000;
            int lo = 0, hi = 1000;
            while (lo < hi) {
                int mid = (lo + hi) >> 1;
                if (L[mid] > kk) lo = mid + 1; else hi = mid;
            }
            g += lo;
        }
        unsigned bits = (unsigned)(kk >> 32);
        unsigned cand = 0xFFFFFFFFu - (unsigned)(d_top[lvl][rk] & 0xFFFFFFFFull);
        int a = (int)(cand / 80u), lab = (int)(cand % 80u);
        const float* rg = (lvl == 0 ? r0 : (lvl == 1 ? r1 : r2)) + (size_t)a * 4;
        int f = (lvl == 0 ? 160 : (lvl == 1 ? 80 : 40));
        float st = (lvl == 0 ? 8.f : (lvl == 1 ? 16.f : 32.f));
        int cell = a / 3, br = a % 3;
        float gx = (float)(cell % f), gy = (float)(cell / f);
        float cx = __fmul_rn(__fadd_rn(sigm(rg[0]), gx), st);
        float cy = __fmul_rn(__fadd_rn(sigm(rg[1]), gy), st);
        float w  = __fmul_rn(xla_expf(rg[2]), c_anch[lvl][br][0]);
        float h  = __fmul_rn(xla_expf(rg[3]), c_anch[lvl][br][1]);
        float x1 = __fsub_rn(cx, __fmul_rn(w, 0.5f));
        float y1 = __fsub_rn(cy, __fmul_rn(h, 0.5f));
        float x2 = __fadd_rn(cx, __fmul_rn(w, 0.5f));
        float y2 = __fadd_rn(cy, __fmul_rn(h, 0.5f));
        out[g * 4 + 0] = x1;   // provisional; zeroed at NMS if rejected
        out[g * 4 + 1] = y1;
        out[g * 4 + 2] = x2;
        out[g * 4 + 3] = y2;
        s_sc[g] = __uint_as_float(bits);
        s_lb[g] = lab;
        float offv = __fmul_rn((float)lab, 10000000.0f);
        float bx1 = __fadd_rn(__fsub_rn(x1, __fmul_rn(x2, 0.5f)), offv);
        float by1 = __fsub_rn(y1, __fmul_rn(y2, 0.5f));
        float bx2 = __fadd_rn(__fadd_rn(x1, __fmul_rn(x2, 0.5f)), offv);
        float by2 = __fadd_rn(y1, __fmul_rn(y2, 0.5f));
        s_nbox[g] = make_float4(bx1, by1, bx2, by2);
        s_ar[g]   = __fmul_rn(__fsub_rn(bx2, bx1), __fsub_rn(by2, by1));
    }
    __syncthreads();

    // per-class greedy NMS: warp w handles classes w, w+32, w+64
    int wid = tid >> 5, lane = tid & 31;
    int* acc = s_acc + wid * ACC_CAP;
    for (int c = wid; c < NCLS; c += 32) {
        int na = 0;
        for (int base = 0; base < K_TOT; base += 32) {
            int r = base + lane;
            unsigned m = __ballot_sync(0xFFFFFFFFu, (r < K_TOT) && (s_lb[r] == c));
            while (m) {
                int b = __ffs(m) - 1;
                m &= m - 1;
                int g0 = base + b;
                float sc = s_sc[g0];
                int keep = 0;
                if (sc > 0.3f) {
                    float4 bi = s_nbox[g0];
                    float  ai = s_ar[g0];
                    bool sup = false;
                    for (int j = lane; j < na; j += 32) {
                        int q = acc[j];
                        float4 bj = s_nbox[q];
                        float xx1 = fmaxf(bi.x, bj.x), yy1 = fmaxf(bi.y, bj.y);
                        float xx2 = fminf(bi.z, bj.z), yy2 = fminf(bi.w, bj.w);
                        float inter = __fmul_rn(fmaxf(1e-10f, __fsub_rn(xx2, xx1)),
                                                fmaxf(1e-10f, __fsub_rn(yy2, yy1)));
                        float denom = __fadd_rn(__fsub_rn(__fadd_rn(ai, s_ar[q]), inter), 1e-14f);
                        if (__fdiv_rn(inter, denom) > 0.5f) sup = true;
                    }
                    sup = __any_sync(0xFFFFFFFFu, sup);
                    if (!sup) {
                        if (lane == 0 && na < ACC_CAP) acc[na] = g0;
                        na++;
                        keep = 1;
                    }
                }
                if (lane == 0) {
                    if (!keep) {
                        out[g0 * 4 + 0] = 0.0f;
                        out[g0 * 4 + 1] = 0.0f;
                        out[g0 * 4 + 2] = 0.0f;
                        out[g0 * 4 + 3] = 0.0f;
                    }
                    out[12000 + g0] = keep ? sc : 0.0f;
                    out[15000 + g0] = keep ? (float)c : -1.0f;
                    out[18000 + g0] = (float)keep;
                }
                __syncwarp();
            }
        }
    }
}

// ---------------- launch ----------------
extern "C" void kernel_launch(void* const* d_in, const int* in_sizes, int n_in,
                              void* d_out, int out_size) {
    const float* obj0 = (const float*)d_in[0];
    const float* cls0 = (const float*)d_in[1];
    const float* reg0 = (const float*)d_in[2];
    const float* obj1 = (const float*)d_in[3];
    const float* cls1 = (const float*)d_in[4];
    const float* reg1 = (const float*)d_in[5];
    const float* obj2 = (const float*)d_in[6];
    const float* cls2 = (const float*)d_in[7];
    const float* reg2 = (const float*)d_in[8];
    float* out = (float*)d_out;

    cudaFuncSetAttribute((const void*)k_sortlvl,
                         cudaFuncAttributeMaxDynamicSharedMemorySize, CAP * 8);
    const int FIN_SMEM = 3008 * 8 + K_TOT * (16 + 4 + 4 + 4) + 32 * ACC_CAP * 4;
    cudaFuncSetAttribute((const void*)k_final,
                         cudaFuncAttributeMaxDynamicSharedMemorySize, FIN_SMEM);

    k_prep<<<(NANCH + 255) / 256, 256>>>(obj0, obj1, obj2);
    k_nop<<<1, 32>>>();
    k_nop<<<1, 32>>>();
    k_filter<<<FILT_GRID, FILT_BLK>>>(cls0, cls1, cls2);   // ncu launch index 3
    k_thresh<<<3, 1024>>>();
    k_sel<<<512, 256>>>(cls0, cls1, cls2);
    k_sortlvl<<<3, 1024, CAP * 8>>>();
    k_final<<<1, 1024, FIN_SMEM>>>(reg0, reg1, reg2, out);
}